// round 13
// baseline (speedup 1.0000x reference)
#include <cuda_runtime.h>
#include <cstdint>

#define FULLMASK 0xFFFFFFFFu
typedef unsigned long long ull;

constexpr int BATCH = 256;
constexpr int HID   = 16;

// ---- packed f32x2 helpers (Blackwell FFMA2 — only reachable via PTX) ----
__device__ __forceinline__ ull pack2(float lo, float hi) {
    ull r; asm("mov.b64 %0, {%1,%2};" : "=l"(r) : "f"(lo), "f"(hi)); return r;
}
__device__ __forceinline__ void unpack2(ull v, float& lo, float& hi) {
    asm("mov.b64 {%0,%1}, %2;" : "=f"(lo), "=f"(hi) : "l"(v));
}
__device__ __forceinline__ ull fma2(ull a, ull b, ull c) {
    ull d; asm("fma.rn.f32x2 %0, %1, %2, %3;" : "=l"(d) : "l"(a), "l"(b), "l"(c)); return d;
}
__device__ __forceinline__ ull add2(ull a, ull b) {
    ull d; asm("add.rn.f32x2 %0, %1, %2;" : "=l"(d) : "l"(a), "l"(b)); return d;
}

// Single-instruction tanh: MUFU.TANH (sm_75+), ~16 cyc. rel_err measured
// 1.04e-5 (R11/R12) against 1e-3 budget.
__device__ __forceinline__ float tanh_fast(float a) {
    float r; asm("tanh.approx.f32 %0, %1;" : "=f"(r) : "f"(a));
    return r;
}

__global__ void __launch_bounds__(32, 1) rnn3_scan_kernel(
    const float* __restrict__ x,        // [B, T, 1]
    const float* __restrict__ prev_h0,  // [2, 16]
    const float* __restrict__ post_h0,  // [1, 1]
    const float* __restrict__ W_ih0,    // [16, 1]
    const float* __restrict__ W_hh0,    // [16, 16]
    const float* __restrict__ b_ih0,    // [16]
    const float* __restrict__ b_hh0,    // [16]
    const float* __restrict__ W_ih1,    // [16, 16]
    const float* __restrict__ W_hh1,    // [16, 16]
    const float* __restrict__ b_ih1,    // [16]
    const float* __restrict__ b_hh1,    // [16]
    const float* __restrict__ W_ihp,    // [1, 16]
    const float* __restrict__ W_hhp,    // [1, 1]
    const float* __restrict__ b_ihp,    // [1]
    const float* __restrict__ b_hhp,    // [1]
    float* __restrict__ out,            // [B, T, 1]
    int T)
{
    const int lane = threadIdx.x;       // 0..31
    const int j    = lane & 15;         // hidden unit owned by this lane
    const int half = lane >> 4;         // 0 = batch A, 1 = batch B
    const int batch = blockIdx.x * 2 + half;

    // Two-slot smem broadcast (WAR distance 2), no hot-loop barrier (R12).
    __shared__ __align__(16) float SH0[2][2][16];
    __shared__ __align__(16) float SH1[2][2][16];

    // ---- register-resident, pair-packed weights ----
    ull whh0p[8], wih1p[8], whh1p[8], wihpp[8];
#pragma unroll
    for (int k = 0; k < 8; k++) {
        whh0p[k] = pack2(__ldg(&W_hh0[j * HID + 2 * k]), __ldg(&W_hh0[j * HID + 2 * k + 1]));
        wih1p[k] = pack2(__ldg(&W_ih1[j * HID + 2 * k]), __ldg(&W_ih1[j * HID + 2 * k + 1]));
        whh1p[k] = pack2(__ldg(&W_hh1[j * HID + 2 * k]), __ldg(&W_hh1[j * HID + 2 * k + 1]));
        wihpp[k] = pack2(__ldg(&W_ihp[2 * k]),           __ldg(&W_ihp[2 * k + 1]));
    }
    const float wih0 = __ldg(&W_ih0[j]);
    const float bh0  = __ldg(&b_ih0[j]) + __ldg(&b_hh0[j]);
    const float bh1  = __ldg(&b_ih1[j]) + __ldg(&b_hh1[j]);
    const float whhp = __ldg(&W_hhp[0]);
    const float bp   = __ldg(&b_ihp[0]) + __ldg(&b_hhp[0]);

    // min-max normalize folded: xn=(x+1)/2 -> wih0*xn + bh0 = wih0h*x + bh0h
    const float wih0h = 0.5f * wih0;
    const float bh0h  = bh0 + wih0h;
    const ull bias1_2 = pack2(bh1, 0.0f);

    // ---- pipeline state: entering iter i, h0p = h0[i-1], h1p = h1[i-2], y = y[i-3]
    ull h0p[8], h1p[8];
#pragma unroll
    for (int k = 0; k < 8; k++) {
        h0p[k] = pack2(__ldg(&prev_h0[2 * k]),       __ldg(&prev_h0[2 * k + 1]));
        h1p[k] = pack2(__ldg(&prev_h0[HID + 2 * k]), __ldg(&prev_h0[HID + 2 * k + 1]));
    }
    float y = __ldg(&post_h0[0]);

    const float* xb = x   + (size_t)batch * T;
    float*       ob = out + (size_t)batch * T;

    // ---- stage helpers: shortened chains (depth-2 fma2 + tree adds) ----
    auto sdot_tanh = [&](ull xb2) -> float {           // layer 0; x-term is the seed
        ull a0 = fma2(whh0p[0], h0p[0], xb2);
        ull a1 = fma2(whh0p[2], h0p[2], 0ULL);
        ull a2 = fma2(whh0p[4], h0p[4], 0ULL);
        ull a3 = fma2(whh0p[6], h0p[6], 0ULL);
        a0 = fma2(whh0p[1], h0p[1], a0);
        a1 = fma2(whh0p[3], h0p[3], a1);
        a2 = fma2(whh0p[5], h0p[5], a2);
        a3 = fma2(whh0p[7], h0p[7], a3);
        ull ss = add2(add2(a0, a1), add2(a2, a3));
        float lo, hi; unpack2(ss, lo, hi);
        return tanh_fast(lo + hi);
    };
    auto tdot_tanh = [&]() -> float {                   // layer 1: 8 chains of depth 2
        ull t0 = fma2(wih1p[0], h0p[0], bias1_2);
        ull t1 = fma2(wih1p[2], h0p[2], 0ULL);
        ull t2 = fma2(wih1p[4], h0p[4], 0ULL);
        ull t3 = fma2(wih1p[6], h0p[6], 0ULL);
        ull t4 = fma2(whh1p[0], h1p[0], 0ULL);
        ull t5 = fma2(whh1p[2], h1p[2], 0ULL);
        ull t6 = fma2(whh1p[4], h1p[4], 0ULL);
        ull t7 = fma2(whh1p[6], h1p[6], 0ULL);
        t0 = fma2(wih1p[1], h0p[1], t0);
        t1 = fma2(wih1p[3], h0p[3], t1);
        t2 = fma2(wih1p[5], h0p[5], t2);
        t3 = fma2(wih1p[7], h0p[7], t3);
        t4 = fma2(whh1p[1], h1p[1], t4);
        t5 = fma2(whh1p[3], h1p[3], t5);
        t6 = fma2(whh1p[5], h1p[5], t6);
        t7 = fma2(whh1p[7], h1p[7], t7);
        ull tt = add2(add2(add2(t0, t1), add2(t2, t3)),
                      add2(add2(t4, t5), add2(t6, t7)));
        float lo, hi; unpack2(tt, lo, hi);
        return tanh_fast(lo + hi);
    };
    auto pdot_tanh = [&]() -> float {                   // post: packed redundant dot on h1p
        ull q0 = fma2(wihpp[0], h1p[0], 0ULL);
        ull q1 = fma2(wihpp[4], h1p[4], 0ULL);
#pragma unroll
        for (int k = 1; k < 4; k++) {
            q0 = fma2(wihpp[k],     h1p[k],     q0);
            q1 = fma2(wihpp[4 + k], h1p[4 + k], q1);
        }
        ull qq = add2(q0, q1);
        float lo, hi; unpack2(qq, lo, hi);
        return tanh_fast((lo + hi) + fmaf(whhp, y, bp));
    };
    auto ldp = [&](ull* dst, const float* bsrc) {
        const ulonglong2* p = (const ulonglong2*)bsrc;
        ulonglong2 a = p[0], b = p[1], c = p[2], d = p[3];
        dst[0] = a.x; dst[1] = a.y; dst[2] = b.x; dst[3] = b.y;
        dst[4] = c.x; dst[5] = c.y; dst[6] = d.x; dst[7] = d.y;
    };

    float yq0 = 0.f, yq1 = 0.f, yq2 = 0.f, yq3 = 0.f;

    // ---- prologue: i = 0..3 (pipeline fill + alignment peel), with barrier ----
    {
        const float4 x03 = *(const float4*)xb;   // x[0..3]
        {   // i = 0: h0[0]
            float h0n = sdot_tanh(pack2(fmaf(wih0h, x03.x, bh0h), 0.0f));
            SH0[0][half][j] = h0n;
            __syncwarp();
            ldp(h0p, SH0[0][half]);
        }
        {   // i = 1: h0[1], h1[0]
            float h0n = sdot_tanh(pack2(fmaf(wih0h, x03.y, bh0h), 0.0f));
            float h1n = tdot_tanh();
            SH0[1][half][j] = h0n;
            SH1[1][half][j] = h1n;
            __syncwarp();
            ldp(h0p, SH0[1][half]);
            ldp(h1p, SH1[1][half]);
        }
        {   // i = 2: h0[2], h1[1], y[0]
            float h0n = sdot_tanh(pack2(fmaf(wih0h, x03.z, bh0h), 0.0f));
            float h1n = tdot_tanh();
            float yn  = pdot_tanh();
            SH0[0][half][j] = h0n;
            SH1[0][half][j] = h1n;
            __syncwarp();
            ldp(h0p, SH0[0][half]);
            ldp(h1p, SH1[0][half]);
            y = yn; yq0 = yn;
        }
        {   // i = 3: h0[3], h1[2], y[1]
            float h0n = sdot_tanh(pack2(fmaf(wih0h, x03.w, bh0h), 0.0f));
            float h1n = tdot_tanh();
            float yn  = pdot_tanh();
            SH0[1][half][j] = h0n;
            SH1[1][half][j] = h1n;
            __syncwarp();
            ldp(h0p, SH0[1][half]);
            ldp(h1p, SH1[1][half]);
            y = yn; yq1 = yn;
        }
    }

    // ---- x prefetch: aligned float4, 2-deep ----
    const float4* X = (const float4*)xb;
    float4 xcur = X[1];                       // x[4..7]
    float4 xnxt = X[2];                       // x[8..11]

    // ---- main loop: tc = 4 .. T-4 step 4; iter i = tc+s computes h0[i], h1[i-1], y[i-2] ----
    for (int tc = 4; tc < T; tc += 4) {
#pragma unroll
        for (int s = 0; s < 4; s++) {
            const int slot = s & 1;           // tc is even
            const float xt = (s == 0) ? xcur.x : (s == 1) ? xcur.y : (s == 2) ? xcur.z : xcur.w;
            const ull xb2 = pack2(fmaf(wih0h, xt, bh0h), 0.0f);   // off-chain (x prefetched)

            // All three stage dots read only OLD state -> mutually independent.
            float h0n = sdot_tanh(xb2);       // -> h0[i]
            SH0[slot][half][j] = h0n;         // store as soon as available
            float h1n = tdot_tanh();          // -> h1[i-1]
            SH1[slot][half][j] = h1n;
            float yn  = pdot_tanh();          // -> y[i-2]  (issues while STS drains)

            // no barrier: same-address RAW enforced by LSU; 2 slots keep
            // the WAR at distance 2.
            ldp(h0p, SH0[slot][half]);
            ldp(h1p, SH1[slot][half]);
            y = yn;

            // y[i-2] lands at queue position (s+2)&3
            if (s == 0) yq2 = yn;
            else if (s == 1) {
                yq3 = yn;
                if (j == 0) *(float4*)(ob + tc - 4) = make_float4(yq0, yq1, yq2, yq3);
            }
            else if (s == 2) yq0 = yn;
            else yq1 = yn;
        }
        xcur = xnxt;
        xnxt = (tc + 8 < T) ? X[tc / 4 + 2] : xnxt;
    }

    // ---- epilogue: i = T (h1[T-1], y[T-2]), i = T+1 (y[T-1]) ----
    {
        float h1n = tdot_tanh();   // h1[T-1]  (h0p=h0[T-1], h1p=h1[T-2])
        float yn  = pdot_tanh();   // y[T-2]
        SH1[0][half][j] = h1n;
        __syncwarp();
        ldp(h1p, SH1[0][half]);
        y = yn; yq2 = yn;
    }
    {
        float yn = pdot_tanh();    // y[T-1]
        yq3 = yn;
        if (j == 0) *(float4*)(ob + T - 4) = make_float4(yq0, yq1, yq2, yq3);
    }
}

extern "C" void kernel_launch(void* const* d_in, const int* in_sizes, int n_in,
                              void* d_out, int out_size)
{
    const float* x       = (const float*)d_in[0];
    const float* prev_h0 = (const float*)d_in[1];
    const float* post_h0 = (const float*)d_in[2];
    const float* W_ih0   = (const float*)d_in[3];
    const float* W_hh0   = (const float*)d_in[4];
    const float* b_ih0   = (const float*)d_in[5];
    const float* b_hh0   = (const float*)d_in[6];
    const float* W_ih1   = (const float*)d_in[7];
    const float* W_hh1   = (const float*)d_in[8];
    const float* b_ih1   = (const float*)d_in[9];
    const float* b_hh1   = (const float*)d_in[10];
    const float* W_ihp   = (const float*)d_in[11];
    const float* W_hhp   = (const float*)d_in[12];
    const float* b_ihp   = (const float*)d_in[13];
    const float* b_hhp   = (const float*)d_in[14];
    float* out = (float*)d_out;

    const int T = in_sizes[0] / BATCH;   // IN == 1, T = 16384 (multiple of 4)

    rnn3_scan_kernel<<<BATCH / 2, 32>>>(
        x, prev_h0, post_h0,
        W_ih0, W_hh0, b_ih0, b_hh0,
        W_ih1, W_hh1, b_ih1, b_hh1,
        W_ihp, W_hhp, b_ihp, b_hhp,
        out, T);
}

// round 14
// speedup vs baseline: 1.4015x; 1.4015x over previous
#include <cuda_runtime.h>
#include <cstdint>

typedef unsigned long long ull;

constexpr int BATCH = 256;
constexpr int HID   = 16;
constexpr int CK    = 32;    // steps per pipeline chunk
constexpr int RB    = 64;    // ring slots = 2 chunks

// ---- packed f32x2 helpers (Blackwell FFMA2 — only reachable via PTX) ----
__device__ __forceinline__ ull pack2(float lo, float hi) {
    ull r; asm("mov.b64 %0, {%1,%2};" : "=l"(r) : "f"(lo), "f"(hi)); return r;
}
__device__ __forceinline__ void unpack2(ull v, float& lo, float& hi) {
    asm("mov.b64 {%0,%1}, %2;" : "=f"(lo), "=f"(hi) : "l"(v));
}
__device__ __forceinline__ ull fma2(ull a, ull b, ull c) {
    ull d; asm("fma.rn.f32x2 %0, %1, %2, %3;" : "=l"(d) : "l"(a), "l"(b), "l"(c)); return d;
}
__device__ __forceinline__ ull add2(ull a, ull b) {
    ull d; asm("add.rn.f32x2 %0, %1, %2;" : "=l"(d) : "l"(a), "l"(b)); return d;
}

// MUFU.TANH (sm_75+), ~16 cyc; rel_err 1.04e-5 proven in R11/R12.
__device__ __forceinline__ float tanh_fast(float a) {
    float r; asm("tanh.approx.f32 %0, %1;" : "=f"(r) : "f"(a));
    return r;
}

// 16-float broadcast vector -> 8 packed ull via 4x LDS.128
__device__ __forceinline__ void ldp16(ull* dst, const float* bsrc) {
    const ulonglong2* p = (const ulonglong2*)bsrc;
    ulonglong2 a = p[0], b = p[1], c = p[2], d = p[3];
    dst[0] = a.x; dst[1] = a.y; dst[2] = b.x; dst[3] = b.y;
    dst[4] = c.x; dst[5] = c.y; dst[6] = d.x; dst[7] = d.y;
}

__global__ void __launch_bounds__(96, 1) rnn3_pipe3_kernel(
    const float* __restrict__ x,        // [B, T, 1]
    const float* __restrict__ prev_h0,  // [2, 16]
    const float* __restrict__ post_h0,  // [1, 1]
    const float* __restrict__ W_ih0,    // [16, 1]
    const float* __restrict__ W_hh0,    // [16, 16]
    const float* __restrict__ b_ih0,    // [16]
    const float* __restrict__ b_hh0,    // [16]
    const float* __restrict__ W_ih1,    // [16, 16]
    const float* __restrict__ W_hh1,    // [16, 16]
    const float* __restrict__ b_ih1,    // [16]
    const float* __restrict__ b_hh1,    // [16]
    const float* __restrict__ W_ihp,    // [1, 16]
    const float* __restrict__ W_hhp,    // [1, 1]
    const float* __restrict__ b_ihp,    // [1]
    const float* __restrict__ b_hhp,    // [1]
    float* __restrict__ out,            // [B, T, 1]
    int T)
{
    const int tid  = threadIdx.x;       // 0..95
    const int wid  = tid >> 5;          // 0 = layer0, 1 = layer1, 2 = post
    const int lane = tid & 31;
    const int j    = lane & 15;         // hidden unit owned by this lane
    const int half = lane >> 4;         // 0 = batch A, 1 = batch B
    const int batch = blockIdx.x * 2 + half;

    // streaming rings: h0 (warp0 -> warp1), h1 (warp1 -> warp2).
    // Writer leads reader by one 32-step chunk; __syncthreads per chunk
    // orders cross-warp access; WAR distance = 64 slots.
    __shared__ __align__(16) float RING0[RB][2][16];
    __shared__ __align__(16) float RING1[RB][2][16];

    const int nCk = T / CK;             // 512

    if (wid == 0) {
        // ===================== warp 0: layer 0 =====================
        ull whh0p[8];
#pragma unroll
        for (int k = 0; k < 8; k++)
            whh0p[k] = pack2(__ldg(&W_hh0[j * HID + 2 * k]), __ldg(&W_hh0[j * HID + 2 * k + 1]));
        // min-max normalize folded: xn=(x+1)/2 -> wih0h*x + bh0h
        const float wih0h = 0.5f * __ldg(&W_ih0[j]);
        const float bh0h  = __ldg(&b_ih0[j]) + __ldg(&b_hh0[j]) + wih0h;

        ull h0p[8];
#pragma unroll
        for (int k = 0; k < 8; k++)
            h0p[k] = pack2(__ldg(&prev_h0[2 * k]), __ldg(&prev_h0[2 * k + 1]));

        const float4* X = (const float4*)(x + (size_t)batch * T);
        float4 xcur = X[0], xnxt = X[1];

        for (int c = 0; c <= nCk + 1; c++) {
            if (c < nCk) {
                const int t0 = c * CK;
#pragma unroll 1
                for (int g = 0; g < CK / 4; g++) {
#pragma unroll
                    for (int s = 0; s < 4; s++) {
                        const int t = t0 + g * 4 + s;
                        const float xt = (s == 0) ? xcur.x : (s == 1) ? xcur.y
                                       : (s == 2) ? xcur.z : xcur.w;
                        const ull xb2 = pack2(fmaf(wih0h, xt, bh0h), 0.0f);
                        // depth-2 chains + tree
                        ull a0 = fma2(whh0p[0], h0p[0], xb2);
                        ull a1 = fma2(whh0p[2], h0p[2], 0ULL);
                        ull a2 = fma2(whh0p[4], h0p[4], 0ULL);
                        ull a3 = fma2(whh0p[6], h0p[6], 0ULL);
                        a0 = fma2(whh0p[1], h0p[1], a0);
                        a1 = fma2(whh0p[3], h0p[3], a1);
                        a2 = fma2(whh0p[5], h0p[5], a2);
                        a3 = fma2(whh0p[7], h0p[7], a3);
                        ull ss = add2(add2(a0, a1), add2(a2, a3));
                        float lo, hi; unpack2(ss, lo, hi);
                        const float h0n = tanh_fast(lo + hi);
                        RING0[t & (RB - 1)][half][j] = h0n;
                        // no barrier: same-address RAW via LSU (R12-proven)
                        ldp16(h0p, RING0[t & (RB - 1)][half]);
                    }
                    xcur = xnxt;
                    const int gn = c * (CK / 4) + g + 2;
                    if (gn < T / 4) xnxt = X[gn];
                }
            }
            __syncthreads();
        }
    } else if (wid == 1) {
        // ===================== warp 1: layer 1 =====================
        ull wih1p[8], whh1p[8];
#pragma unroll
        for (int k = 0; k < 8; k++) {
            wih1p[k] = pack2(__ldg(&W_ih1[j * HID + 2 * k]), __ldg(&W_ih1[j * HID + 2 * k + 1]));
            whh1p[k] = pack2(__ldg(&W_hh1[j * HID + 2 * k]), __ldg(&W_hh1[j * HID + 2 * k + 1]));
        }
        const ull bias1_2 = pack2(__ldg(&b_ih1[j]) + __ldg(&b_hh1[j]), 0.0f);

        ull h1p[8];
#pragma unroll
        for (int k = 0; k < 8; k++)
            h1p[k] = pack2(__ldg(&prev_h0[HID + 2 * k]), __ldg(&prev_h0[HID + 2 * k + 1]));

        for (int c = 0; c <= nCk + 1; c++) {
            if (c >= 1 && c <= nCk) {
                const int t0 = (c - 1) * CK;
                // parity double-buffered h0 prefetch (takes ring0 LDS off-chain)
                ull h0v[2][8];
                ldp16(h0v[0], RING0[t0 & (RB - 1)][half]);
#pragma unroll 4
                for (int s = 0; s < CK; s++) {
                    const int p = s & 1;
                    const int t = t0 + s;
                    if (s + 1 < CK)
                        ldp16(h0v[p ^ 1], RING0[(t + 1) & (RB - 1)][half]);

                    // u-chains (slack path, h0v ready) + h1-chains (critical)
                    ull u0 = fma2(wih1p[0], h0v[p][0], bias1_2);
                    ull u1 = fma2(wih1p[2], h0v[p][2], 0ULL);
                    ull u2 = fma2(wih1p[4], h0v[p][4], 0ULL);
                    ull u3 = fma2(wih1p[6], h0v[p][6], 0ULL);
                    u0 = fma2(wih1p[1], h0v[p][1], u0);
                    u1 = fma2(wih1p[3], h0v[p][3], u1);
                    u2 = fma2(wih1p[5], h0v[p][5], u2);
                    u3 = fma2(wih1p[7], h0v[p][7], u3);
                    ull uu = add2(add2(u0, u1), add2(u2, u3));

                    ull v0 = fma2(whh1p[0], h1p[0], 0ULL);
                    ull v1 = fma2(whh1p[2], h1p[2], 0ULL);
                    ull v2 = fma2(whh1p[4], h1p[4], 0ULL);
                    ull v3 = fma2(whh1p[6], h1p[6], 0ULL);
                    v0 = fma2(whh1p[1], h1p[1], v0);
                    v1 = fma2(whh1p[3], h1p[3], v1);
                    v2 = fma2(whh1p[5], h1p[5], v2);
                    v3 = fma2(whh1p[7], h1p[7], v3);
                    ull vv = add2(add2(v0, v1), add2(v2, v3));

                    ull tt = add2(uu, vv);
                    float lo, hi; unpack2(tt, lo, hi);
                    const float h1n = tanh_fast(lo + hi);

                    RING1[t & (RB - 1)][half][j] = h1n;
                    ldp16(h1p, RING1[t & (RB - 1)][half]);
                }
            }
            __syncthreads();
        }
    } else {
        // ===================== warp 2: post layer =====================
        ull wihpp[8];
#pragma unroll
        for (int k = 0; k < 8; k++)
            wihpp[k] = pack2(__ldg(&W_ihp[2 * k]), __ldg(&W_ihp[2 * k + 1]));
        const float whhp = __ldg(&W_hhp[0]);
        const float bp   = __ldg(&b_ihp[0]) + __ldg(&b_hhp[0]);

        float y = __ldg(&post_h0[0]);
        float* ob = out + (size_t)batch * T;
        float yq0 = 0.f, yq1 = 0.f, yq2 = 0.f;

        for (int c = 0; c <= nCk + 1; c++) {
            if (c >= 2) {
                const int t0 = (c - 2) * CK;
                ull h1v[2][8];
                ldp16(h1v[0], RING1[t0 & (RB - 1)][half]);
#pragma unroll 4
                for (int s = 0; s < CK; s++) {
                    const int p = s & 1;
                    const int t = t0 + s;
                    if (s + 1 < CK)
                        ldp16(h1v[p ^ 1], RING1[(t + 1) & (RB - 1)][half]);

                    // redundant packed dot (slack) + short y chain (critical)
                    ull q0 = fma2(wihpp[0], h1v[p][0], 0ULL);
                    ull q1 = fma2(wihpp[4], h1v[p][4], 0ULL);
#pragma unroll
                    for (int k = 1; k < 4; k++) {
                        q0 = fma2(wihpp[k],     h1v[p][k],     q0);
                        q1 = fma2(wihpp[4 + k], h1v[p][4 + k], q1);
                    }
                    ull qq = add2(q0, q1);
                    float lo, hi; unpack2(qq, lo, hi);
                    y = tanh_fast((lo + hi) + fmaf(whhp, y, bp));

                    const int q4 = s & 3;
                    if (q4 == 0) yq0 = y;
                    else if (q4 == 1) yq1 = y;
                    else if (q4 == 2) yq2 = y;
                    else if (j == 0)
                        *(float4*)(ob + t - 3) = make_float4(yq0, yq1, yq2, y);
                }
            }
            __syncthreads();
        }
    }
}

extern "C" void kernel_launch(void* const* d_in, const int* in_sizes, int n_in,
                              void* d_out, int out_size)
{
    const float* x       = (const float*)d_in[0];
    const float* prev_h0 = (const float*)d_in[1];
    const float* post_h0 = (const float*)d_in[2];
    const float* W_ih0   = (const float*)d_in[3];
    const float* W_hh0   = (const float*)d_in[4];
    const float* b_ih0   = (const float*)d_in[5];
    const float* b_hh0   = (const float*)d_in[6];
    const float* W_ih1   = (const float*)d_in[7];
    const float* W_hh1   = (const float*)d_in[8];
    const float* b_ih1   = (const float*)d_in[9];
    const float* b_hh1   = (const float*)d_in[10];
    const float* W_ihp   = (const float*)d_in[11];
    const float* W_hhp   = (const float*)d_in[12];
    const float* b_ihp   = (const float*)d_in[13];
    const float* b_hhp   = (const float*)d_in[14];
    float* out = (float*)d_out;

    const int T = in_sizes[0] / BATCH;   // IN == 1, T = 16384 (multiple of CK)

    rnn3_pipe3_kernel<<<BATCH / 2, 96>>>(
        x, prev_h0, post_h0,
        W_ih0, W_hh0, b_ih0, b_hh0,
        W_ih1, W_hh1, b_ih1, b_hh1,
        W_ihp, W_hhp, b_ihp, b_hhp,
        out, T);
}